// round 4
// baseline (speedup 1.0000x reference)
#include <cuda_runtime.h>
#include <math.h>

// GaussianKernel: B=16, N=256, T=128, K=128, H=16
// phi(s) is a scalar->R^16 function => tabulate + lerp.

#define Bc 16
#define Nc 256
#define Tc 128
#define Kc 128
#define Hc 16
#define TBL 4096

__device__ unsigned g_enc_min;
__device__ unsigned g_enc_max;
__device__ int g_tok64;   // 1 if tokens buffer is int64, 0 if int32
__device__ __align__(16) float g_table[TBL * Hc];

// order-preserving float <-> uint encoding (for atomicMin/Max over signed floats)
__device__ __forceinline__ unsigned enc_f(float f) {
    unsigned u = __float_as_uint(f);
    return (u & 0x80000000u) ? ~u : (u | 0x80000000u);
}
__device__ __forceinline__ float dec_f(unsigned e) {
    unsigned u = (e & 0x80000000u) ? (e ^ 0x80000000u) : ~e;
    return __uint_as_float(u);
}

// nan_to_num(nan/inf/-inf -> 0), robust under --use_fast_math (no isfinite)
__device__ __forceinline__ float sanitize(float v) {
    unsigned u = __float_as_uint(v);
    return ((u & 0x7f800000u) == 0x7f800000u) ? 0.0f : v;
}

__device__ __forceinline__ int get_token(const int* __restrict__ tok, int i, int is64) {
    // little-endian: int64 low word holds the value (values in [0,T), non-negative)
    return is64 ? tok[2 * i] : tok[i];
}

__global__ void init_k(const int* __restrict__ tok32) {
    g_enc_min = 0xFFFFFFFFu;
    g_enc_max = 0u;
    // Detect int64 vs int32 tokens: if int64, every high word over the first 64
    // entries is zero. Genuine int32 tokens ~U[0,128) make that impossible.
    int allzero = 1;
    for (int i = 0; i < 64; i++) {
        if (tok32[2 * i + 1] != 0) { allzero = 0; break; }
    }
    g_tok64 = allzero;
}

__global__ void minmax_k(const float* __restrict__ d,
                         const int* __restrict__ tok,
                         const float* __restrict__ gamma_t,
                         const float* __restrict__ beta_t) {
    const int total = Bc * Nc * Nc;
    const int is64 = g_tok64;
    unsigned lmin = 0xFFFFFFFFu, lmax = 0u;
    for (int idx = blockIdx.x * blockDim.x + threadIdx.x; idx < total;
         idx += gridDim.x * blockDim.x) {
        int m = idx & (Nc - 1);
        int n = (idx >> 8) & (Nc - 1);
        int b = idx >> 16;
        int ti = get_token(tok, b * Nc + n, is64);
        int tj = get_token(tok, b * Nc + m, is64);
        float g  = gamma_t[ti * Tc + tj];
        float be = beta_t[ti * Tc + tj];
        float dv = sanitize(d[idx]);
        float s = fmaf(g, dv, be);
        unsigned e = enc_f(s);
        lmin = min(lmin, e);
        lmax = max(lmax, e);
    }
    #pragma unroll
    for (int o = 16; o > 0; o >>= 1) {
        lmin = min(lmin, __shfl_xor_sync(0xffffffffu, lmin, o));
        lmax = max(lmax, __shfl_xor_sync(0xffffffffu, lmax, o));
    }
    __shared__ unsigned smin_s[8], smax_s[8];
    int w = threadIdx.x >> 5, l = threadIdx.x & 31;
    if (l == 0) { smin_s[w] = lmin; smax_s[w] = lmax; }
    __syncthreads();
    if (threadIdx.x == 0) {
        unsigned a = 0xFFFFFFFFu, c = 0u;
        int nw = blockDim.x >> 5;
        for (int i = 0; i < nw; i++) { a = min(a, smin_s[i]); c = max(c, smax_s[i]); }
        atomicMin(&g_enc_min, a);
        atomicMax(&g_enc_max, c);
    }
}

// One 128-thread block evaluates the exact network at table grid points.
__global__ void build_k(const float* __restrict__ mu,
                        const float* __restrict__ log_sigma,
                        const float* __restrict__ W1,
                        const float* __restrict__ b1,
                        const float* __restrict__ W2,
                        const float* __restrict__ b2) {
    __shared__ float psi_s[Kc];
    __shared__ float h_s[Kc];
    const int j = threadIdx.x;            // 0..127
    const float smin = dec_f(g_enc_min);
    const float smax = dec_f(g_enc_max);
    const float step = (smax - smin) * (1.0f / (float)(TBL - 1));

    // per-thread constants for its Gaussian component
    float ls   = log_sigma[j];
    float sig  = fmaxf(ls, 0.0f) + log1pf(expf(-fabsf(ls))) + 1e-6f;  // softplus + eps
    float inv  = 1.0f / sig;
    float coef = 0.3989422804014327f * inv;   // 1/sqrt(2*pi) / sigma
    float muj  = mu[j];
    float b1j  = b1[j];
    float b2j  = (j < Hc) ? b2[j] : 0.0f;

    for (int e = blockIdx.x; e < TBL; e += gridDim.x) {
        float s = fmaf((float)e, step, smin);
        float x = (s - muj) * inv;
        psi_s[j] = expf(-0.5f * x * x) * coef;
        __syncthreads();
        float acc = b1j;
        #pragma unroll 8
        for (int k = 0; k < Kc; k++) acc = fmaf(psi_s[k], W1[k * Kc + j], acc);
        h_s[j] = fmaxf(acc, 0.0f);
        __syncthreads();
        if (j < Hc) {
            float p = b2j;
            #pragma unroll 8
            for (int k = 0; k < Kc; k++) p = fmaf(h_s[k], W2[k * Hc + j], p);
            g_table[e * Hc + j] = p;
        }
        __syncthreads();
    }
}

// One block per (b, n) row; thread m handles one position, lerps 16 outputs.
__global__ void apply_k(const float* __restrict__ d,
                        const int* __restrict__ tok,
                        const float* __restrict__ gamma_t,
                        const float* __restrict__ beta_t,
                        float* __restrict__ out) {
    const int bn = blockIdx.x;            // 0..B*N-1
    const int n  = bn & (Nc - 1);
    const int b  = bn >> 8;
    const int m  = threadIdx.x;
    const int is64 = g_tok64;

    const float smin  = dec_f(g_enc_min);
    const float smax  = dec_f(g_enc_max);
    const float scale = (float)(TBL - 1) / fmaxf(smax - smin, 1e-30f);

    int ti = get_token(tok, b * Nc + n, is64);
    int tj = get_token(tok, b * Nc + m, is64);
    float g  = gamma_t[ti * Tc + tj];
    float be = beta_t[ti * Tc + tj];
    float dv = sanitize(d[(size_t)bn * Nc + m]);
    float s = fmaf(g, dv, be);

    float t = (s - smin) * scale;
    t = fminf(fmaxf(t, 0.0f), (float)(TBL - 1));
    int i = (int)t;
    if (i > TBL - 2) i = TBL - 2;
    float f = t - (float)i;

    const float4* r0 = reinterpret_cast<const float4*>(g_table + i * Hc);
    const float4* r1 = reinterpret_cast<const float4*>(g_table + (i + 1) * Hc);

    size_t base = (size_t)b * (Hc * Nc * Nc) + (size_t)n * Nc + m;
    #pragma unroll
    for (int q = 0; q < 4; q++) {
        float4 a = r0[q];
        float4 c = r1[q];
        out[base + (size_t)(4 * q + 0) * (Nc * Nc)] = fmaf(f, c.x - a.x, a.x);
        out[base + (size_t)(4 * q + 1) * (Nc * Nc)] = fmaf(f, c.y - a.y, a.y);
        out[base + (size_t)(4 * q + 2) * (Nc * Nc)] = fmaf(f, c.z - a.z, a.z);
        out[base + (size_t)(4 * q + 3) * (Nc * Nc)] = fmaf(f, c.w - a.w, a.w);
    }
}

extern "C" void kernel_launch(void* const* d_in, const int* in_sizes, int n_in,
                              void* d_out, int out_size) {
    const float* d         = (const float*)d_in[0];
    const int*   tokens    = (const int*)d_in[1];   // int32 or int64 (auto-detected)
    const float* mu        = (const float*)d_in[2];
    const float* log_sigma = (const float*)d_in[3];
    const float* W1        = (const float*)d_in[4];
    const float* b1        = (const float*)d_in[5];
    const float* W2        = (const float*)d_in[6];
    const float* b2        = (const float*)d_in[7];
    const float* gamma_t   = (const float*)d_in[8];
    const float* beta_t    = (const float*)d_in[9];
    float* out = (float*)d_out;

    init_k<<<1, 1>>>(tokens);
    minmax_k<<<1024, 256>>>(d, tokens, gamma_t, beta_t);
    build_k<<<512, 128>>>(mu, log_sigma, W1, b1, W2, b2);
    apply_k<<<Bc * Nc, 256>>>(d, tokens, gamma_t, beta_t, out);
}

// round 6
// speedup vs baseline: 1.2317x; 1.2317x over previous
#include <cuda_runtime.h>
#include <math.h>

// GaussianKernel: B=16, N=256, T=128, K=128, H=16
// phi(s) is scalar->R^16 => tabulate (TBL entries) + lerp from SMEM-resident table.

#define Bc 16
#define Nc 256
#define Tc 128
#define Kc 128
#define Hc 16
#define TBL 2048
#define APPLY_BLOCKS 152
#define APPLY_THREADS 1024

__device__ unsigned g_enc_min;
__device__ unsigned g_enc_max;
__device__ __align__(16) float g_table[TBL * Hc];

// order-preserving float <-> uint encoding (for atomicMin/Max over signed floats)
__device__ __forceinline__ unsigned enc_f(float f) {
    unsigned u = __float_as_uint(f);
    return (u & 0x80000000u) ? ~u : (u | 0x80000000u);
}
__device__ __forceinline__ float dec_f(unsigned e) {
    unsigned u = (e & 0x80000000u) ? (e ^ 0x80000000u) : ~e;
    return __uint_as_float(u);
}

// nan_to_num(nan/inf/-inf -> 0), robust under --use_fast_math (no isfinite)
__device__ __forceinline__ float sanitize(float v) {
    unsigned u = __float_as_uint(v);
    return ((u & 0x7f800000u) == 0x7f800000u) ? 0.0f : v;
}

// Block-cooperative detection of int64 vs int32 token buffer.
// int64 little-endian: all high words zero. Genuine uniform int32 tokens in
// [0,128) cannot have 64 consecutive odd-position words all zero (p ~ 2^-448).
__device__ __forceinline__ int detect_tok64(const int* __restrict__ tok) {
    int pred = (threadIdx.x < 64) ? (tok[2 * threadIdx.x + 1] == 0) : 1;
    return __syncthreads_and(pred);
}

__global__ void reset_k() {
    g_enc_min = 0xFFFFFFFFu;
    g_enc_max = 0u;
}

__global__ void minmax_k(const float* __restrict__ d,
                         const int* __restrict__ tok,
                         const float* __restrict__ gamma_t,
                         const float* __restrict__ beta_t) {
    const int is64 = detect_tok64(tok);
    const int total = Bc * Nc * Nc;
    unsigned lmin = 0xFFFFFFFFu, lmax = 0u;
    for (int idx = blockIdx.x * blockDim.x + threadIdx.x; idx < total;
         idx += gridDim.x * blockDim.x) {
        int m = idx & (Nc - 1);
        int n = (idx >> 8) & (Nc - 1);
        int b = idx >> 16;
        int ti = is64 ? tok[2 * (b * Nc + n)] : tok[b * Nc + n];
        int tj = is64 ? tok[2 * (b * Nc + m)] : tok[b * Nc + m];
        float g  = gamma_t[ti * Tc + tj];
        float be = beta_t[ti * Tc + tj];
        float dv = sanitize(d[idx]);
        float s = fmaf(g, dv, be);
        unsigned e = enc_f(s);
        lmin = min(lmin, e);
        lmax = max(lmax, e);
    }
    #pragma unroll
    for (int o = 16; o > 0; o >>= 1) {
        lmin = min(lmin, __shfl_xor_sync(0xffffffffu, lmin, o));
        lmax = max(lmax, __shfl_xor_sync(0xffffffffu, lmax, o));
    }
    __shared__ unsigned smin_s[8], smax_s[8];
    int w = threadIdx.x >> 5, l = threadIdx.x & 31;
    if (l == 0) { smin_s[w] = lmin; smax_s[w] = lmax; }
    __syncthreads();
    if (threadIdx.x == 0) {
        unsigned a = 0xFFFFFFFFu, c = 0u;
        int nw = blockDim.x >> 5;
        for (int i = 0; i < nw; i++) { a = min(a, smin_s[i]); c = max(c, smax_s[i]); }
        atomicMin(&g_enc_min, a);
        atomicMax(&g_enc_max, c);
    }
}

// One 128-thread block evaluates the exact network at table grid points.
__global__ void build_k(const float* __restrict__ mu,
                        const float* __restrict__ log_sigma,
                        const float* __restrict__ W1,
                        const float* __restrict__ b1,
                        const float* __restrict__ W2,
                        const float* __restrict__ b2) {
    __shared__ float psi_s[Kc];
    __shared__ float h_s[Kc];
    const int j = threadIdx.x;            // 0..127
    const float smin = dec_f(g_enc_min);
    const float smax = dec_f(g_enc_max);
    const float step = (smax - smin) * (1.0f / (float)(TBL - 1));

    float ls   = log_sigma[j];
    float sig  = fmaxf(ls, 0.0f) + log1pf(expf(-fabsf(ls))) + 1e-6f;  // softplus + eps
    float inv  = 1.0f / sig;
    float coef = 0.3989422804014327f * inv;   // 1/sqrt(2*pi) / sigma
    float muj  = mu[j];
    float b1j  = b1[j];
    float b2j  = (j < Hc) ? b2[j] : 0.0f;

    for (int e = blockIdx.x; e < TBL; e += gridDim.x) {
        float s = fmaf((float)e, step, smin);
        float x = (s - muj) * inv;
        psi_s[j] = expf(-0.5f * x * x) * coef;
        __syncthreads();
        float acc = b1j;
        #pragma unroll 8
        for (int k = 0; k < Kc; k++) acc = fmaf(psi_s[k], W1[k * Kc + j], acc);
        h_s[j] = fmaxf(acc, 0.0f);
        __syncthreads();
        if (j < Hc) {
            float p = b2j;
            #pragma unroll 8
            for (int k = 0; k < Kc; k++) p = fmaf(h_s[k], W2[k * Hc + j], p);
            g_table[e * Hc + j] = p;
        }
        __syncthreads();
    }
}

// SMEM bank-swizzle for the table: chunk c (16B) of row i lives at float4
// index i*4 + (c ^ ((i>>2)&3)). Combined with the (i&1)-driven half-crossbar
// split, an LDS.128 with random row indices spreads over 8 bank groups.
__device__ __forceinline__ int sw_idx(int i, int c) {
    return (i << 2) + (c ^ ((i >> 2) & 3));
}

// Persistent kernel: 1 block/SM, table cached in 128 KB of dynamic smem.
__global__ void __launch_bounds__(APPLY_THREADS, 1)
apply_k(const float* __restrict__ d,
        const int* __restrict__ tok,
        const float* __restrict__ gamma_t,
        const float* __restrict__ beta_t,
        float* __restrict__ out) {
    extern __shared__ float4 tbl4[];
    const int tid = threadIdx.x;
    const int is64 = detect_tok64(tok);

    // stage table into smem (swizzled)
    const float4* gt4 = reinterpret_cast<const float4*>(g_table);
    for (int j = tid; j < TBL * 4; j += APPLY_THREADS) {
        int i = j >> 2, c = j & 3;
        tbl4[sw_idx(i, c)] = gt4[j];
    }
    __syncthreads();

    const float smin  = dec_f(g_enc_min);
    const float smax  = dec_f(g_enc_max);
    const float scale = (float)(TBL - 1) / fmaxf(smax - smin, 1e-30f);
    const int total = Bc * Nc * Nc;

    for (int idx = blockIdx.x * APPLY_THREADS + tid; idx < total;
         idx += gridDim.x * APPLY_THREADS) {
        int m = idx & (Nc - 1);
        int n = (idx >> 8) & (Nc - 1);
        int b = idx >> 16;
        int ti = is64 ? tok[2 * (b * Nc + n)] : tok[b * Nc + n];
        int tj = is64 ? tok[2 * (b * Nc + m)] : tok[b * Nc + m];
        float g  = gamma_t[ti * Tc + tj];
        float be = beta_t[ti * Tc + tj];
        float dv = sanitize(d[idx]);
        float s = fmaf(g, dv, be);

        float t = fminf(fmaxf((s - smin) * scale, 0.0f), (float)(TBL - 1));
        int i0 = (int)t;
        if (i0 > TBL - 2) i0 = TBL - 2;
        float f = t - (float)i0;
        int i1 = i0 + 1;

        float4 a[4], c4[4];
        #pragma unroll
        for (int c = 0; c < 4; c++) a[c]  = tbl4[sw_idx(i0, c)];
        #pragma unroll
        for (int c = 0; c < 4; c++) c4[c] = tbl4[sw_idx(i1, c)];

        size_t base = (size_t)b * (Hc * Nc * Nc) + (size_t)n * Nc + m;
        #pragma unroll
        for (int q = 0; q < 4; q++) {
            out[base + (size_t)(4 * q + 0) * (Nc * Nc)] = fmaf(f, c4[q].x - a[q].x, a[q].x);
            out[base + (size_t)(4 * q + 1) * (Nc * Nc)] = fmaf(f, c4[q].y - a[q].y, a[q].y);
            out[base + (size_t)(4 * q + 2) * (Nc * Nc)] = fmaf(f, c4[q].z - a[q].z, a[q].z);
            out[base + (size_t)(4 * q + 3) * (Nc * Nc)] = fmaf(f, c4[q].w - a[q].w, a[q].w);
        }
    }
}

extern "C" void kernel_launch(void* const* d_in, const int* in_sizes, int n_in,
                              void* d_out, int out_size) {
    const float* d         = (const float*)d_in[0];
    const int*   tokens    = (const int*)d_in[1];   // int32 or int64 (auto-detected)
    const float* mu        = (const float*)d_in[2];
    const float* log_sigma = (const float*)d_in[3];
    const float* W1        = (const float*)d_in[4];
    const float* b1        = (const float*)d_in[5];
    const float* W2        = (const float*)d_in[6];
    const float* b2        = (const float*)d_in[7];
    const float* gamma_t   = (const float*)d_in[8];
    const float* beta_t    = (const float*)d_in[9];
    float* out = (float*)d_out;

    static int attr_done = 0;
    if (!attr_done) {
        cudaFuncSetAttribute(apply_k, cudaFuncAttributeMaxDynamicSharedMemorySize,
                             TBL * Hc * (int)sizeof(float));
        attr_done = 1;
    }

    reset_k<<<1, 1>>>();
    minmax_k<<<1024, 256>>>(d, tokens, gamma_t, beta_t);
    build_k<<<512, 128>>>(mu, log_sigma, W1, b1, W2, b2);
    apply_k<<<APPLY_BLOCKS, APPLY_THREADS, TBL * Hc * (int)sizeof(float)>>>(
        d, tokens, gamma_t, beta_t, out);
}

// round 8
// speedup vs baseline: 1.4899x; 1.2096x over previous
#include <cuda_runtime.h>
#include <math.h>

// GaussianKernel: B=16, N=256, T=128, K=128, H=16
// phi(s) is scalar->R^16 => tabulate (TBL entries) + lerp from SMEM-resident table.

#define Bc 16
#define Nc 256
#define Tc 128
#define Kc 128
#define Hc 16
#define TBL 1024
#define MM_BLOCKS 512
#define MM_THREADS 256
#define BUILD_BLOCKS 512
#define APPLY_BLOCKS 304
#define APPLY_THREADS 1024

__device__ unsigned g_dmin_part[MM_BLOCKS];
__device__ unsigned g_dmax_part[MM_BLOCKS];
__device__ unsigned g_gb[4];          // enc: gamma_min, gamma_max, beta_min, beta_max
__device__ float g_smin_f, g_scale_f;
__device__ __align__(16) float g_table[TBL * Hc];

// order-preserving float <-> uint encoding
__device__ __forceinline__ unsigned enc_f(float f) {
    unsigned u = __float_as_uint(f);
    return (u & 0x80000000u) ? ~u : (u | 0x80000000u);
}
__device__ __forceinline__ float dec_f(unsigned e) {
    unsigned u = (e & 0x80000000u) ? (e ^ 0x80000000u) : ~e;
    return __uint_as_float(u);
}

// nan_to_num(nan/inf/-inf -> 0), robust under --use_fast_math (no isfinite)
__device__ __forceinline__ float sanitize(float v) {
    unsigned u = __float_as_uint(v);
    return ((u & 0x7f800000u) == 0x7f800000u) ? 0.0f : v;
}

// int64 vs int32 token buffer detection (block-cooperative, blockDim >= 64)
__device__ __forceinline__ int detect_tok64(const int* __restrict__ tok) {
    int pred = (threadIdx.x < 64) ? (tok[2 * threadIdx.x + 1] == 0) : 1;
    return __syncthreads_and(pred);
}

// block reduce (min of emin, max of emax) for <=256 threads; result in lane 0 of warp 0
__device__ __forceinline__ void block_minmax(unsigned& emin, unsigned& emax,
                                             unsigned* smin_s, unsigned* smax_s) {
    #pragma unroll
    for (int o = 16; o > 0; o >>= 1) {
        emin = min(emin, __shfl_xor_sync(0xffffffffu, emin, o));
        emax = max(emax, __shfl_xor_sync(0xffffffffu, emax, o));
    }
    int w = threadIdx.x >> 5, l = threadIdx.x & 31;
    if (l == 0) { smin_s[w] = emin; smax_s[w] = emax; }
    __syncthreads();
    if (threadIdx.x == 0) {
        int nw = blockDim.x >> 5;
        for (int i = 1; i < nw; i++) {
            emin = min(emin, smin_s[i]);
            emax = max(emax, smax_s[i]);
        }
    }
}

// Pure coalesced scan: per-block min/max of sanitized d. Blocks 0/1 also scan
// gamma/beta tables. No gathers, no atomics (partials reduced in build_k).
__global__ void minmax_k(const float4* __restrict__ d4,
                         const float* __restrict__ gamma_t,
                         const float* __restrict__ beta_t) {
    __shared__ unsigned smin_s[8], smax_s[8];
    const int total4 = (Bc * Nc * Nc) / 4;
    unsigned lmin = 0xFFFFFFFFu, lmax = 0u;
    for (int i = blockIdx.x * blockDim.x + threadIdx.x; i < total4;
         i += gridDim.x * blockDim.x) {
        float4 v = d4[i];
        unsigned e;
        e = enc_f(sanitize(v.x)); lmin = min(lmin, e); lmax = max(lmax, e);
        e = enc_f(sanitize(v.y)); lmin = min(lmin, e); lmax = max(lmax, e);
        e = enc_f(sanitize(v.z)); lmin = min(lmin, e); lmax = max(lmax, e);
        e = enc_f(sanitize(v.w)); lmin = min(lmin, e); lmax = max(lmax, e);
    }
    block_minmax(lmin, lmax, smin_s, smax_s);
    if (threadIdx.x == 0) {
        g_dmin_part[blockIdx.x] = lmin;
        g_dmax_part[blockIdx.x] = lmax;
    }
    // blocks 0/1: bounds of gamma/beta tables (16384 floats each)
    if (blockIdx.x < 2) {
        const float* tab = (blockIdx.x == 0) ? gamma_t : beta_t;
        unsigned tmin = 0xFFFFFFFFu, tmax = 0u;
        for (int i = threadIdx.x; i < Tc * Tc; i += blockDim.x) {
            unsigned e = enc_f(tab[i]);
            tmin = min(tmin, e);
            tmax = max(tmax, e);
        }
        __syncthreads();
        block_minmax(tmin, tmax, smin_s, smax_s);
        if (threadIdx.x == 0) {
            g_gb[2 * blockIdx.x]     = tmin;
            g_gb[2 * blockIdx.x + 1] = tmax;
        }
    }
}

// Reduce partials -> conservative s-bounds, then tabulate the exact network.
__global__ void build_k(const float* __restrict__ mu,
                        const float* __restrict__ log_sigma,
                        const float* __restrict__ W1,
                        const float* __restrict__ b1,
                        const float* __restrict__ W2,
                        const float* __restrict__ b2) {
    __shared__ float psi_s[Kc];
    __shared__ float h_s[Kc];
    __shared__ float bounds_s[2];
    const int j = threadIdx.x;            // 0..127

    // reduce the 512 d-partials (4 per thread)
    {
        __shared__ unsigned smin_s[8], smax_s[8];
        unsigned lmin = 0xFFFFFFFFu, lmax = 0u;
        #pragma unroll
        for (int q = 0; q < 4; q++) {
            int i = j + q * 128;
            lmin = min(lmin, g_dmin_part[i]);
            lmax = max(lmax, g_dmax_part[i]);
        }
        block_minmax(lmin, lmax, smin_s, smax_s);
        if (j == 0) {
            float dlo = dec_f(lmin), dhi = dec_f(lmax);
            float glo = dec_f(g_gb[0]), ghi = dec_f(g_gb[1]);
            float blo = dec_f(g_gb[2]), bhi = dec_f(g_gb[3]);
            float p1 = glo * dlo, p2 = glo * dhi, p3 = ghi * dlo, p4 = ghi * dhi;
            float pmin = fminf(fminf(p1, p2), fminf(p3, p4));
            float pmax = fmaxf(fmaxf(p1, p2), fmaxf(p3, p4));
            float smin = pmin + blo;
            float smax = pmax + bhi;
            bounds_s[0] = smin;
            bounds_s[1] = smax;
            if (blockIdx.x == 0) {
                g_smin_f  = smin;
                g_scale_f = (float)(TBL - 1) / fmaxf(smax - smin, 1e-30f);
            }
        }
        __syncthreads();
    }
    const float smin = bounds_s[0];
    const float step = (bounds_s[1] - smin) * (1.0f / (float)(TBL - 1));

    float ls   = log_sigma[j];
    float sig  = fmaxf(ls, 0.0f) + log1pf(expf(-fabsf(ls))) + 1e-6f;  // softplus + eps
    float inv  = 1.0f / sig;
    float coef = 0.3989422804014327f * inv;   // 1/sqrt(2*pi) / sigma
    float muj  = mu[j];
    float b1j  = b1[j];
    float b2j  = (j < Hc) ? b2[j] : 0.0f;

    for (int e = blockIdx.x; e < TBL; e += gridDim.x) {
        float s = fmaf((float)e, step, smin);
        float x = (s - muj) * inv;
        psi_s[j] = expf(-0.5f * x * x) * coef;
        __syncthreads();
        float a0 = b1j, a1 = 0.0f;
        #pragma unroll 8
        for (int k = 0; k < Kc; k += 2) {
            a0 = fmaf(psi_s[k],     W1[k * Kc + j],       a0);
            a1 = fmaf(psi_s[k + 1], W1[(k + 1) * Kc + j], a1);
        }
        h_s[j] = fmaxf(a0 + a1, 0.0f);
        __syncthreads();
        if (j < Hc) {
            float p0 = b2j, p1 = 0.0f;
            #pragma unroll 8
            for (int k = 0; k < Kc; k += 2) {
                p0 = fmaf(h_s[k],     W2[k * Hc + j],       p0);
                p1 = fmaf(h_s[k + 1], W2[(k + 1) * Hc + j], p1);
            }
            g_table[e * Hc + j] = p0 + p1;
        }
        __syncthreads();
    }
}

// SMEM bank-swizzle: 16B chunk c of row i lives at float4 index i*4 + (c ^ ((i>>2)&3)).
__device__ __forceinline__ int sw_idx(int i, int c) {
    return (i << 2) + (c ^ ((i >> 2) & 3));
}

// 2 blocks/SM (64 KB smem each), 64 warps/SM. Chunk-pair lerp keeps regs <= 32.
__global__ void __launch_bounds__(APPLY_THREADS, 2)
apply_k(const float* __restrict__ d,
        const int* __restrict__ tok,
        const float* __restrict__ gamma_t,
        const float* __restrict__ beta_t,
        float* __restrict__ out) {
    extern __shared__ float4 tbl4[];
    const int tid = threadIdx.x;
    const int is64 = detect_tok64(tok);

    // stage table into smem (swizzled)
    const float4* gt4 = reinterpret_cast<const float4*>(g_table);
    for (int j = tid; j < TBL * 4; j += APPLY_THREADS) {
        int i = j >> 2, c = j & 3;
        tbl4[sw_idx(i, c)] = gt4[j];
    }
    __syncthreads();

    const float smin  = g_smin_f;
    const float scale = g_scale_f;
    const int total = Bc * Nc * Nc;

    for (int idx = blockIdx.x * APPLY_THREADS + tid; idx < total;
         idx += gridDim.x * APPLY_THREADS) {
        int m = idx & (Nc - 1);
        int n = (idx >> 8) & (Nc - 1);
        int b = idx >> 16;
        int ti = is64 ? tok[2 * (b * Nc + n)] : tok[b * Nc + n];
        int tj = is64 ? tok[2 * (b * Nc + m)] : tok[b * Nc + m];
        float g  = gamma_t[ti * Tc + tj];
        float be = beta_t[ti * Tc + tj];
        float dv = sanitize(d[idx]);
        float s = fmaf(g, dv, be);

        float t = fminf(fmaxf((s - smin) * scale, 0.0f), (float)(TBL - 1));
        int i0 = (int)t;
        if (i0 > TBL - 2) i0 = TBL - 2;
        float f = t - (float)i0;
        int i1 = i0 + 1;

        float* po = out + ((size_t)b * (Hc * Nc * Nc) + (size_t)n * Nc + m);
        #pragma unroll
        for (int cp = 0; cp < 2; cp++) {
            int c0 = 2 * cp, c1 = 2 * cp + 1;
            float4 a0 = tbl4[sw_idx(i0, c0)];
            float4 e0 = tbl4[sw_idx(i1, c0)];
            float4 a1 = tbl4[sw_idx(i0, c1)];
            float4 e1 = tbl4[sw_idx(i1, c1)];
            po[(size_t)(4 * c0 + 0) * (Nc * Nc)] = fmaf(f, e0.x - a0.x, a0.x);
            po[(size_t)(4 * c0 + 1) * (Nc * Nc)] = fmaf(f, e0.y - a0.y, a0.y);
            po[(size_t)(4 * c0 + 2) * (Nc * Nc)] = fmaf(f, e0.z - a0.z, a0.z);
            po[(size_t)(4 * c0 + 3) * (Nc * Nc)] = fmaf(f, e0.w - a0.w, a0.w);
            po[(size_t)(4 * c1 + 0) * (Nc * Nc)] = fmaf(f, e1.x - a1.x, a1.x);
            po[(size_t)(4 * c1 + 1) * (Nc * Nc)] = fmaf(f, e1.y - a1.y, a1.y);
            po[(size_t)(4 * c1 + 2) * (Nc * Nc)] = fmaf(f, e1.z - a1.z, a1.z);
            po[(size_t)(4 * c1 + 3) * (Nc * Nc)] = fmaf(f, e1.w - a1.w, a1.w);
        }
    }
}

extern "C" void kernel_launch(void* const* d_in, const int* in_sizes, int n_in,
                              void* d_out, int out_size) {
    const float* d         = (const float*)d_in[0];
    const int*   tokens    = (const int*)d_in[1];   // int32 or int64 (auto-detected)
    const float* mu        = (const float*)d_in[2];
    const float* log_sigma = (const float*)d_in[3];
    const float* W1        = (const float*)d_in[4];
    const float* b1        = (const float*)d_in[5];
    const float* W2        = (const float*)d_in[6];
    const float* b2        = (const float*)d_in[7];
    const float* gamma_t   = (const float*)d_in[8];
    const float* beta_t    = (const float*)d_in[9];
    float* out = (float*)d_out;

    static int attr_done = 0;
    if (!attr_done) {
        cudaFuncSetAttribute(apply_k, cudaFuncAttributeMaxDynamicSharedMemorySize,
                             TBL * Hc * (int)sizeof(float));
        attr_done = 1;
    }

    minmax_k<<<MM_BLOCKS, MM_THREADS>>>((const float4*)d, gamma_t, beta_t);
    build_k<<<BUILD_BLOCKS, 128>>>(mu, log_sigma, W1, b1, W2, b2);
    apply_k<<<APPLY_BLOCKS, APPLY_THREADS, TBL * Hc * (int)sizeof(float)>>>(
        d, tokens, gamma_t, beta_t, out);
}

// round 13
// speedup vs baseline: 1.6350x; 1.0974x over previous
#include <cuda_runtime.h>
#include <math.h>

// GaussianKernel: B=16, N=256, T=128, K=128, H=16
// phi(s) is scalar->R^16 => tabulate (TBL entries) + lerp from SMEM-resident table.

#define Bc 16
#define Nc 256
#define Tc 128
#define Kc 128
#define Hc 16
#define TBL 1024
#define MM_BLOCKS 512
#define MM_THREADS 256
#define BUILD_BLOCKS 512
#define APPLY_BLOCKS 304
#define APPLY_THREADS 1024

__device__ unsigned g_dmin_part[MM_BLOCKS];
__device__ unsigned g_dmax_part[MM_BLOCKS];
__device__ unsigned g_gmin_part[MM_BLOCKS];
__device__ unsigned g_gmax_part[MM_BLOCKS];
__device__ unsigned g_bmin_part[MM_BLOCKS];
__device__ unsigned g_bmax_part[MM_BLOCKS];
__device__ float g_smin_f, g_scale_f;
__device__ __align__(16) float g_table[TBL * Hc];

// order-preserving float <-> uint encoding
__device__ __forceinline__ unsigned enc_f(float f) {
    unsigned u = __float_as_uint(f);
    return (u & 0x80000000u) ? ~u : (u | 0x80000000u);
}
__device__ __forceinline__ float dec_f(unsigned e) {
    unsigned u = (e & 0x80000000u) ? (e ^ 0x80000000u) : ~e;
    return __uint_as_float(u);
}

// nan_to_num(nan/inf/-inf -> 0), robust under --use_fast_math (no isfinite)
__device__ __forceinline__ float sanitize(float v) {
    unsigned u = __float_as_uint(v);
    return ((u & 0x7f800000u) == 0x7f800000u) ? 0.0f : v;
}

// int64 vs int32 token buffer detection (block-cooperative, blockDim >= 64)
__device__ __forceinline__ int detect_tok64(const int* __restrict__ tok) {
    int pred = (threadIdx.x < 64) ? (tok[2 * threadIdx.x + 1] == 0) : 1;
    return __syncthreads_and(pred);
}

// block reduce (min of emin, max of emax); result valid in thread 0
__device__ __forceinline__ void block_minmax(unsigned& emin, unsigned& emax,
                                             unsigned* smin_s, unsigned* smax_s) {
    #pragma unroll
    for (int o = 16; o > 0; o >>= 1) {
        emin = min(emin, __shfl_xor_sync(0xffffffffu, emin, o));
        emax = max(emax, __shfl_xor_sync(0xffffffffu, emax, o));
    }
    int w = threadIdx.x >> 5, l = threadIdx.x & 31;
    if (l == 0) { smin_s[w] = emin; smax_s[w] = emax; }
    __syncthreads();
    if (threadIdx.x == 0) {
        int nw = blockDim.x >> 5;
        for (int i = 1; i < nw; i++) {
            emin = min(emin, smin_s[i]);
            emax = max(emax, smax_s[i]);
        }
    }
}

__device__ __forceinline__ void mm4(float4 v, unsigned& lmin, unsigned& lmax, int san) {
    unsigned e;
    e = enc_f(san ? sanitize(v.x) : v.x); lmin = min(lmin, e); lmax = max(lmax, e);
    e = enc_f(san ? sanitize(v.y) : v.y); lmin = min(lmin, e); lmax = max(lmax, e);
    e = enc_f(san ? sanitize(v.z) : v.z); lmin = min(lmin, e); lmax = max(lmax, e);
    e = enc_f(san ? sanitize(v.w) : v.w); lmin = min(lmin, e); lmax = max(lmax, e);
}

// Pure coalesced scan; work uniformly distributed (no straggler blocks).
// Each block: 2 float4 of d per thread + an 8-float4 slice of gamma and beta.
__global__ void minmax_k(const float4* __restrict__ d4,
                         const float4* __restrict__ gamma4,
                         const float4* __restrict__ beta4) {
    __shared__ unsigned smin_s[8], smax_s[8];
    const int total4 = (Bc * Nc * Nc) / 4;     // 262144
    const int gb4 = (Tc * Tc) / 4;             // 4096 float4 per table
    const int per_blk = gb4 / MM_BLOCKS;       // 8

    unsigned dmin = 0xFFFFFFFFu, dmax = 0u;
    unsigned gmin = 0xFFFFFFFFu, gmax = 0u;
    unsigned bmin = 0xFFFFFFFFu, bmax = 0u;

    // gamma/beta slice: threads 0..per_blk-1 take one float4 each (parallel
    // with the d loads below — all independent)
    if (threadIdx.x < per_blk) {
        int i = blockIdx.x * per_blk + threadIdx.x;
        mm4(gamma4[i], gmin, gmax, 0);
        mm4(beta4[i],  bmin, bmax, 0);
    }

    for (int i = blockIdx.x * blockDim.x + threadIdx.x; i < total4;
         i += gridDim.x * blockDim.x) {
        mm4(d4[i], dmin, dmax, 1);
    }

    block_minmax(dmin, dmax, smin_s, smax_s);
    if (threadIdx.x == 0) { g_dmin_part[blockIdx.x] = dmin; g_dmax_part[blockIdx.x] = dmax; }
    __syncthreads();
    block_minmax(gmin, gmax, smin_s, smax_s);
    if (threadIdx.x == 0) { g_gmin_part[blockIdx.x] = gmin; g_gmax_part[blockIdx.x] = gmax; }
    __syncthreads();
    block_minmax(bmin, bmax, smin_s, smax_s);
    if (threadIdx.x == 0) { g_bmin_part[blockIdx.x] = bmin; g_bmax_part[blockIdx.x] = bmax; }
}

// Reduce partials -> conservative s-bounds, then tabulate the exact network.
__global__ void build_k(const float* __restrict__ mu,
                        const float* __restrict__ log_sigma,
                        const float* __restrict__ W1,
                        const float* __restrict__ b1,
                        const float* __restrict__ W2,
                        const float* __restrict__ b2) {
    __shared__ float psi_s[Kc];
    __shared__ float h_s[Kc];
    __shared__ float bounds_s[2];
    const int j = threadIdx.x;            // 0..127

    // reduce the 512-entry partial arrays (4 per thread each)
    {
        __shared__ unsigned smin_s[8], smax_s[8];
        unsigned dmin = 0xFFFFFFFFu, dmax = 0u;
        unsigned gmin = 0xFFFFFFFFu, gmax = 0u;
        unsigned bmin = 0xFFFFFFFFu, bmax = 0u;
        #pragma unroll
        for (int q = 0; q < 4; q++) {
            int i = j + q * 128;
            dmin = min(dmin, g_dmin_part[i]); dmax = max(dmax, g_dmax_part[i]);
            gmin = min(gmin, g_gmin_part[i]); gmax = max(gmax, g_gmax_part[i]);
            bmin = min(bmin, g_bmin_part[i]); bmax = max(bmax, g_bmax_part[i]);
        }
        block_minmax(dmin, dmax, smin_s, smax_s);
        __syncthreads();
        block_minmax(gmin, gmax, smin_s, smax_s);
        __syncthreads();
        block_minmax(bmin, bmax, smin_s, smax_s);
        if (j == 0) {
            float dlo = dec_f(dmin), dhi = dec_f(dmax);
            float glo = dec_f(gmin), ghi = dec_f(gmax);
            float blo = dec_f(bmin), bhi = dec_f(bmax);
            float p1 = glo * dlo, p2 = glo * dhi, p3 = ghi * dlo, p4 = ghi * dhi;
            float pmin = fminf(fminf(p1, p2), fminf(p3, p4));
            float pmax = fmaxf(fmaxf(p1, p2), fmaxf(p3, p4));
            float smin = pmin + blo;
            float smax = pmax + bhi;
            bounds_s[0] = smin;
            bounds_s[1] = smax;
            if (blockIdx.x == 0) {
                g_smin_f  = smin;
                g_scale_f = (float)(TBL - 1) / fmaxf(smax - smin, 1e-30f);
            }
        }
        __syncthreads();
    }
    const float smin = bounds_s[0];
    const float step = (bounds_s[1] - smin) * (1.0f / (float)(TBL - 1));

    float ls   = log_sigma[j];
    float sig  = fmaxf(ls, 0.0f) + log1pf(expf(-fabsf(ls))) + 1e-6f;  // softplus + eps
    float inv  = 1.0f / sig;
    float coef = 0.3989422804014327f * inv;   // 1/sqrt(2*pi) / sigma
    float muj  = mu[j];
    float b1j  = b1[j];
    float b2j  = (j < Hc) ? b2[j] : 0.0f;

    for (int e = blockIdx.x; e < TBL; e += gridDim.x) {
        float s = fmaf((float)e, step, smin);
        float x = (s - muj) * inv;
        psi_s[j] = expf(-0.5f * x * x) * coef;
        __syncthreads();
        float a0 = b1j, a1 = 0.0f;
        #pragma unroll 8
        for (int k = 0; k < Kc; k += 2) {
            a0 = fmaf(psi_s[k],     W1[k * Kc + j],       a0);
            a1 = fmaf(psi_s[k + 1], W1[(k + 1) * Kc + j], a1);
        }
        h_s[j] = fmaxf(a0 + a1, 0.0f);
        __syncthreads();
        if (j < Hc) {
            float p0 = b2j, p1 = 0.0f;
            #pragma unroll 8
            for (int k = 0; k < Kc; k += 2) {
                p0 = fmaf(h_s[k],     W2[k * Hc + j],       p0);
                p1 = fmaf(h_s[k + 1], W2[(k + 1) * Hc + j], p1);
            }
            g_table[e * Hc + j] = p0 + p1;
        }
        __syncthreads();
    }
}

// SMEM bank-swizzle: 16B chunk c of row i lives at float4 index i*4 + (c ^ ((i>>2)&3)).
__device__ __forceinline__ int sw_idx(int i, int c) {
    return (i << 2) + (c ^ ((i >> 2) & 3));
}

// 2 blocks/SM (64 KB smem each), 64 warps/SM. Chunk-pair lerp keeps regs <= 32.
// Output uses streaming stores (write-once 67 MB; don't pollute L2).
__global__ void __launch_bounds__(APPLY_THREADS, 2)
apply_k(const float* __restrict__ d,
        const int* __restrict__ tok,
        const float* __restrict__ gamma_t,
        const float* __restrict__ beta_t,
        float* __restrict__ out) {
    extern __shared__ float4 tbl4[];
    const int tid = threadIdx.x;
    const int is64 = detect_tok64(tok);

    // stage table into smem (swizzled)
    const float4* gt4 = reinterpret_cast<const float4*>(g_table);
    for (int j = tid; j < TBL * 4; j += APPLY_THREADS) {
        int i = j >> 2, c = j & 3;
        tbl4[sw_idx(i, c)] = gt4[j];
    }
    __syncthreads();

    const float smin  = g_smin_f;
    const float scale = g_scale_f;
    const int total = Bc * Nc * Nc;

    for (int idx = blockIdx.x * APPLY_THREADS + tid; idx < total;
         idx += gridDim.x * APPLY_THREADS) {
        int m = idx & (Nc - 1);
        int n = (idx >> 8) & (Nc - 1);
        int b = idx >> 16;
        int ti = is64 ? tok[2 * (b * Nc + n)] : tok[b * Nc + n];
        int tj = is64 ? tok[2 * (b * Nc + m)] : tok[b * Nc + m];
        float g  = gamma_t[ti * Tc + tj];
        float be = beta_t[ti * Tc + tj];
        float dv = sanitize(d[idx]);
        float s = fmaf(g, dv, be);

        float t = fminf(fmaxf((s - smin) * scale, 0.0f), (float)(TBL - 1));
        int i0 = (int)t;
        if (i0 > TBL - 2) i0 = TBL - 2;
        float f = t - (float)i0;
        int i1 = i0 + 1;

        float* po = out + ((size_t)b * (Hc * Nc * Nc) + (size_t)n * Nc + m);
        #pragma unroll
        for (int cp = 0; cp < 2; cp++) {
            int c0 = 2 * cp, c1 = 2 * cp + 1;
            float4 a0 = tbl4[sw_idx(i0, c0)];
            float4 e0 = tbl4[sw_idx(i1, c0)];
            float4 a1 = tbl4[sw_idx(i0, c1)];
            float4 e1 = tbl4[sw_idx(i1, c1)];
            __stcs(po + (size_t)(4 * c0 + 0) * (Nc * Nc), fmaf(f, e0.x - a0.x, a0.x));
            __stcs(po + (size_t)(4 * c0 + 1) * (Nc * Nc), fmaf(f, e0.y - a0.y, a0.y));
            __stcs(po + (size_t)(4 * c0 + 2) * (Nc * Nc), fmaf(f, e0.z - a0.z, a0.z));
            __stcs(po + (size_t)(4 * c0 + 3) * (Nc * Nc), fmaf(f, e0.w - a0.w, a0.w));
            __stcs(po + (size_t)(4 * c1 + 0) * (Nc * Nc), fmaf(f, e1.x - a1.x, a1.x));
            __stcs(po + (size_t)(4 * c1 + 1) * (Nc * Nc), fmaf(f, e1.y - a1.y, a1.y));
            __stcs(po + (size_t)(4 * c1 + 2) * (Nc * Nc), fmaf(f, e1.z - a1.z, a1.z));
            __stcs(po + (size_t)(4 * c1 + 3) * (Nc * Nc), fmaf(f, e1.w - a1.w, a1.w));
        }
    }
}

extern "C" void kernel_launch(void* const* d_in, const int* in_sizes, int n_in,
                              void* d_out, int out_size) {
    const float* d         = (const float*)d_in[0];
    const int*   tokens    = (const int*)d_in[1];   // int32 or int64 (auto-detected)
    const float* mu        = (const float*)d_in[2];
    const float* log_sigma = (const float*)d_in[3];
    const float* W1        = (const float*)d_in[4];
    const float* b1        = (const float*)d_in[5];
    const float* W2        = (const float*)d_in[6];
    const float* b2        = (const float*)d_in[7];
    const float* gamma_t   = (const float*)d_in[8];
    const float* beta_t    = (const float*)d_in[9];
    float* out = (float*)d_out;

    static int attr_done = 0;
    if (!attr_done) {
        cudaFuncSetAttribute(apply_k, cudaFuncAttributeMaxDynamicSharedMemorySize,
                             TBL * Hc * (int)sizeof(float));
        attr_done = 1;
    }

    minmax_k<<<MM_BLOCKS, MM_THREADS>>>((const float4*)d,
                                        (const float4*)gamma_t,
                                        (const float4*)beta_t);
    build_k<<<BUILD_BLOCKS, 128>>>(mu, log_sigma, W1, b1, W2, b2);
    apply_k<<<APPLY_BLOCKS, APPLY_THREADS, TBL * Hc * (int)sizeof(float)>>>(
        d, tokens, gamma_t, beta_t, out);
}